// round 12
// baseline (speedup 1.0000x reference)
#include <cuda_runtime.h>
#include <cuda_bf16.h>
#include <math.h>

// Shapes
#define BB 16
#define NN 256
#define DD 256
#define HH 8
#define HD 32
#define PD 4
#define RATIO 4
#define ROWS (BB*NN)            // 4096
#define PAIR_ROWS (BB*NN*NN)    // 1048576

// ---------------- scratch (device globals, no allocation) ----------------
__device__ float g_xn [ROWS*DD];        // 4 MB
__device__ float g_qkv[ROWS*3*DD];      // 12 MB
__device__ float g_biasT[BB*HH*NN*NN];  // 33.5 MB  [B,H,N,N]
__device__ float g_xa [ROWS*DD];        // 4 MB  [B,N,H*HD]
__device__ float g_x1 [ROWS*DD];        // 4 MB
__device__ float g_m1 [ROWS*RATIO*DD];  // 16 MB

// Branchless gelu via Abramowitz-Stegun 7.1.26 erf (|eps| <= 1.5e-7).
__device__ __forceinline__ float gelu_exact(float x) {
    float z  = x * 0.70710678118654752f;
    float az = fabsf(z);
    float t  = __fdividef(1.0f, fmaf(0.3275911f, az, 1.0f));
    float p  = t*(0.254829592f + t*(-0.284496736f + t*(1.421413741f
                  + t*(-1.453152027f + t*1.061405429f))));
    float e  = __expf(-az*az);
    float erfv = copysignf(fmaf(-p, e, 1.0f), z);
    return 0.5f*x*(1.0f + erfv);
}

__device__ __forceinline__ unsigned f2tf32(float x) {
    unsigned r;
    asm("cvt.rna.tf32.f32 %0, %1;" : "=r"(r) : "f"(x));
    return r;
}

__device__ __forceinline__ void mma_tf32(
    float& c0, float& c1, float& c2, float& c3,
    unsigned a0, unsigned a1, unsigned a2, unsigned a3,
    unsigned b0, unsigned b1)
{
    asm volatile(
        "mma.sync.aligned.m16n8k8.row.col.f32.tf32.tf32.f32 "
        "{%0,%1,%2,%3}, {%4,%5,%6,%7}, {%8,%9}, {%0,%1,%2,%3};"
        : "+f"(c0), "+f"(c1), "+f"(c2), "+f"(c3)
        : "r"(a0), "r"(a1), "r"(a2), "r"(a3), "r"(b0), "r"(b1));
}

__device__ __forceinline__ unsigned sptr(const void* p) {
    return (unsigned)__cvta_generic_to_shared(p);
}
__device__ __forceinline__ void cp16(unsigned s, const float* g) {
    asm volatile("cp.async.cg.shared.global [%0], [%1], 16;" :: "r"(s), "l"(g));
}

// ---------------- pairwise MLP (tf32 tensor cores) ----------------
#define H1S 68   // smem row stride for h1 (conflict-free fragment loads)
__global__ __launch_bounds__(256) void pairwise_kernel(
    const float* __restrict__ u,
    const float* __restrict__ w1, const float* __restrict__ b1,
    const float* __restrict__ w2, const float* __restrict__ b2,
    const float* __restrict__ w3, const float* __restrict__ b3,
    float* __restrict__ biasOut)
{
    extern __shared__ float dsm[];
    unsigned* h1s = (unsigned*)dsm;                 // 128*68
    unsigned* w2f = h1s + 128*H1S;                  // 4096 (fragment layout)
    float*    w3s = (float*)(w2f + 4096);           // 512
    float*    b2s = w3s + 512;                      // 64
    float*    b3s = b2s + 64;                       // 8
    float*    w1s = b3s + 8;                        // 256
    float*    b1s = w1s + 256;                      // 64

    int tid = threadIdx.x;
    int lane = tid & 31, warp = tid >> 5;
    int tig = lane & 3, gid = lane >> 2;

    if (tid < 64)  b1s[tid] = b1[tid];
    if (tid < 64)  b2s[tid] = b2[tid];
    if (tid < 8)   b3s[tid] = b3[tid];
    w1s[tid] = w1[tid];
    for (int i = tid; i < 512; i += 256) w3s[i] = w3[i];
    for (int idx = tid; idx < 4096; idx += 256) {
        int tile = idx >> 6;          // kt*8 + nt
        int pos  = idx & 63;
        int l    = pos >> 1, which = pos & 1;
        int kt = tile >> 3, nt = tile & 7;
        int ltig = l & 3, lgid = l >> 2;
        int k = kt*8 + ltig + which*4;
        int n = nt*8 + lgid;
        w2f[tile*64 + l*2 + which] = f2tf32(w2[k*64 + n]);
    }

    {
        int row = tid >> 1;                 // 0..127
        int c0  = (tid & 1) * 32;
        long gr = (long)blockIdx.x * 128 + row;
        float4 uv = ((const float4*)u)[gr];
        unsigned* dst = h1s + row*H1S + c0;
#pragma unroll
        for (int cc = 0; cc < 32; cc += 4) {
            unsigned pk[4];
#pragma unroll
            for (int q = 0; q < 4; q++) {
                int c = c0 + cc + q;
                float t = b1s[c] + uv.x*w1s[c] + uv.y*w1s[64+c]
                                 + uv.z*w1s[128+c] + uv.w*w1s[192+c];
                pk[q] = f2tf32(gelu_exact(t));
            }
            *(uint4*)&dst[cc] = make_uint4(pk[0], pk[1], pk[2], pk[3]);
        }
    }
    __syncthreads();

    float c[8][4];
#pragma unroll
    for (int nt = 0; nt < 8; nt++)
#pragma unroll
        for (int q = 0; q < 4; q++) c[nt][q] = 0.f;

    const unsigned* h1w = h1s + (warp*16 + gid)*H1S;
#pragma unroll
    for (int kt = 0; kt < 8; kt++) {
        unsigned a0 = h1w[kt*8 + tig];
        unsigned a1 = h1w[8*H1S + kt*8 + tig];
        unsigned a2 = h1w[kt*8 + tig + 4];
        unsigned a3 = h1w[8*H1S + kt*8 + tig + 4];
        const uint2* bf = (const uint2*)(w2f + kt*8*64);
#pragma unroll
        for (int nt = 0; nt < 8; nt++) {
            uint2 b = bf[nt*32 + lane];
            mma_tf32(c[nt][0], c[nt][1], c[nt][2], c[nt][3],
                     a0, a1, a2, a3, b.x, b.y);
        }
    }

    float acc0[8], acc1[8];
#pragma unroll
    for (int h = 0; h < 8; h++) { acc0[h] = 0.f; acc1[h] = 0.f; }

#pragma unroll
    for (int nt = 0; nt < 8; nt++) {
        int col0 = nt*8 + tig*2;
        float g00 = gelu_exact(c[nt][0] + b2s[col0]);
        float g01 = gelu_exact(c[nt][1] + b2s[col0+1]);
        float g10 = gelu_exact(c[nt][2] + b2s[col0]);
        float g11 = gelu_exact(c[nt][3] + b2s[col0+1]);
        const float4* w3r = (const float4*)&w3s[col0*8];
        float4 wa0 = w3r[0], wa1 = w3r[1];
        float4 wb0 = w3r[2], wb1 = w3r[3];
        acc0[0] += g00*wa0.x + g01*wb0.x;  acc1[0] += g10*wa0.x + g11*wb0.x;
        acc0[1] += g00*wa0.y + g01*wb0.y;  acc1[1] += g10*wa0.y + g11*wb0.y;
        acc0[2] += g00*wa0.z + g01*wb0.z;  acc1[2] += g10*wa0.z + g11*wb0.z;
        acc0[3] += g00*wa0.w + g01*wb0.w;  acc1[3] += g10*wa0.w + g11*wb0.w;
        acc0[4] += g00*wa1.x + g01*wb1.x;  acc1[4] += g10*wa1.x + g11*wb1.x;
        acc0[5] += g00*wa1.y + g01*wb1.y;  acc1[5] += g10*wa1.y + g11*wb1.y;
        acc0[6] += g00*wa1.z + g01*wb1.z;  acc1[6] += g10*wa1.z + g11*wb1.z;
        acc0[7] += g00*wa1.w + g01*wb1.w;  acc1[7] += g10*wa1.w + g11*wb1.w;
    }

#pragma unroll
    for (int h = 0; h < 8; h++) {
        acc0[h] += __shfl_xor_sync(0xffffffffu, acc0[h], 1);
        acc1[h] += __shfl_xor_sync(0xffffffffu, acc1[h], 1);
    }
#pragma unroll
    for (int h = 0; h < 8; h++) {
        acc0[h] += __shfl_xor_sync(0xffffffffu, acc0[h], 2);
        acc1[h] += __shfl_xor_sync(0xffffffffu, acc1[h], 2);
    }

    long R0 = (long)blockIdx.x * 128 + warp*16 + gid;
    int b = (int)(R0 >> 16);
    int i = (int)((R0 >> 8) & 255);
    int j0 = (int)(R0 & 255);
    int hA = tig*2, hB = hA + 1;

    float oA0 = gelu_exact(acc0[hA] + b3s[hA]);
    float oB0 = gelu_exact(acc0[hB] + b3s[hB]);
    float oA1 = gelu_exact(acc1[hA] + b3s[hA]);
    float oB1 = gelu_exact(acc1[hB] + b3s[hB]);

    long baseA = ((long)(b*8 + hA) << 16) + (i << 8);
    long baseB = ((long)(b*8 + hB) << 16) + (i << 8);
    biasOut[baseA + j0]     = oA0;
    biasOut[baseB + j0]     = oB0;
    biasOut[baseA + j0 + 8] = oA1;
    biasOut[baseB + j0 + 8] = oB1;
}

// ---------------- LayerNorm ----------------
__global__ __launch_bounds__(256) void ln_kernel(
    const float* __restrict__ x, const float* __restrict__ g,
    const float* __restrict__ bb, float* __restrict__ out)
{
    __shared__ float red[16];
    int r = blockIdx.x, t = threadIdx.x;
    float v = x[r*256 + t];

    float s = v;
#pragma unroll
    for (int o = 16; o > 0; o >>= 1) s += __shfl_xor_sync(0xffffffffu, s, o);
    if ((t & 31) == 0) red[t >> 5] = s;
    __syncthreads();
    float mu = 0.f;
#pragma unroll
    for (int w = 0; w < 8; w++) mu += red[w];
    mu *= (1.0f/256.0f);

    float d = v - mu;
    float q = d*d;
#pragma unroll
    for (int o = 16; o > 0; o >>= 1) q += __shfl_xor_sync(0xffffffffu, q, o);
    if ((t & 31) == 0) red[8 + (t >> 5)] = q;
    __syncthreads();
    float var = 0.f;
#pragma unroll
    for (int w = 0; w < 8; w++) var += red[8 + w];
    var *= (1.0f/256.0f);

    out[r*256 + t] = d * rsqrtf(var + 1e-5f) * g[t] + bb[t];
}

// ---------------- tf32 tensor-core GEMM (cp.async double-buffered) ----------
#define AS_STRIDE 36
#define BS_STRIDE 72
#define A_BUF (128*AS_STRIDE)
#define B_BUF (32*BS_STRIDE)
#define TG_SMEM ((2*A_BUF + 2*B_BUF)*4)
template<int EPI>
__global__ __launch_bounds__(256, 2) void tgemm_kernel(
    const float* __restrict__ A, const float* __restrict__ Bm,
    const float* __restrict__ bias, const float* __restrict__ res,
    float* __restrict__ C, int M, int Nn, int K)
{
    extern __shared__ float tsm[];
    float* As = tsm;                 // 2 bufs of 128*36
    float* Bs = tsm + 2*A_BUF;       // 2 bufs of 32*72

    int tid = threadIdx.x;
    int lane = tid & 31, warp = tid >> 5;
    int tig = lane & 3, gid = lane >> 2;
    int warp_m = warp & 3, warp_n = warp >> 2;

    int row0 = blockIdx.y * 128;
    int col0 = blockIdx.x * 64;

    int ar = tid >> 1, ac = (tid & 1) * 16;
    int br = tid >> 3, bc = (tid & 7) * 8;

    const float* Ap = A + (long)(row0 + ar)*K + ac;
    const float* Bp = Bm + (long)br*Nn + col0 + bc;

    unsigned a_sb = sptr(&As[ar*AS_STRIDE + ac]);
    unsigned b_sb = sptr(&Bs[br*BS_STRIDE + bc]);

    float c[2][4][4];
#pragma unroll
    for (int mt = 0; mt < 2; mt++)
#pragma unroll
        for (int nt = 0; nt < 4; nt++)
#pragma unroll
            for (int q = 0; q < 4; q++) c[mt][nt][q] = 0.f;

    int iters = K >> 5;

    {
        const float* ag = Ap;
#pragma unroll
        for (int i = 0; i < 4; i++) cp16(a_sb + 16*i, ag + 4*i);
        const float* bg = Bp;
#pragma unroll
        for (int i = 0; i < 2; i++) cp16(b_sb + 16*i, bg + 4*i);
        asm volatile("cp.async.commit_group;");
    }

    for (int it = 0; it < iters; it++) {
        int buf = it & 1;
        if (it + 1 < iters) {
            int nbuf = buf ^ 1;
            const float* ag = Ap + (it + 1)*32;
#pragma unroll
            for (int i = 0; i < 4; i++) cp16(a_sb + nbuf*A_BUF*4 + 16*i, ag + 4*i);
            const float* bg = Bp + (long)(it + 1)*32*Nn;
#pragma unroll
            for (int i = 0; i < 2; i++) cp16(b_sb + nbuf*B_BUF*4 + 16*i, bg + 4*i);
            asm volatile("cp.async.commit_group;");
            asm volatile("cp.async.wait_group 1;");
        } else {
            asm volatile("cp.async.wait_group 0;");
        }
        __syncthreads();

        const float* aw0 = As + buf*A_BUF + (warp_m*32 + gid)*AS_STRIDE;
        const float* bw  = Bs + buf*B_BUF + warp_n*32 + gid;
#pragma unroll
        for (int kt = 0; kt < 4; kt++) {
            unsigned af[2][4];
#pragma unroll
            for (int mt = 0; mt < 2; mt++) {
                const float* aw = aw0 + mt*16*AS_STRIDE + kt*8;
                af[mt][0] = f2tf32(aw[tig]);
                af[mt][1] = f2tf32(aw[8*AS_STRIDE + tig]);
                af[mt][2] = f2tf32(aw[tig + 4]);
                af[mt][3] = f2tf32(aw[8*AS_STRIDE + tig + 4]);
            }
#pragma unroll
            for (int nt = 0; nt < 4; nt++) {
                const float* bww = bw + (kt*8 + tig)*BS_STRIDE + nt*8;
                unsigned b0 = f2tf32(bww[0]);
                unsigned b1 = f2tf32(bww[4*BS_STRIDE]);
#pragma unroll
                for (int mt = 0; mt < 2; mt++)
                    mma_tf32(c[mt][nt][0], c[mt][nt][1], c[mt][nt][2], c[mt][nt][3],
                             af[mt][0], af[mt][1], af[mt][2], af[mt][3], b0, b1);
            }
        }
        __syncthreads();
    }

#pragma unroll
    for (int mt = 0; mt < 2; mt++) {
#pragma unroll
        for (int half = 0; half < 2; half++) {
            int r = row0 + warp_m*32 + mt*16 + gid + half*8;
#pragma unroll
            for (int nt = 0; nt < 4; nt++) {
                int cc = col0 + warp_n*32 + nt*8 + tig*2;
                float v0 = c[mt][nt][half*2 + 0] + bias[cc];
                float v1 = c[mt][nt][half*2 + 1] + bias[cc + 1];
                if (EPI == 1 || EPI == 3) { v0 = gelu_exact(v0); v1 = gelu_exact(v1); }
                if (EPI == 2 || EPI == 3) {
                    const float2 rr = *(const float2*)&res[(long)r*Nn + cc];
                    v0 += rr.x; v1 += rr.y;
                }
                *(float2*)&C[(long)r*Nn + cc] = make_float2(v0, v1);
            }
        }
    }
}

// ---------------- Fused attention v5: 4-row iterations, transposed V --------
// grid = 256 (2 blocks per (b,h)), block = 512 (16 warps).
// One pass of K (score loop) and of V (PV loop) serves 4 query rows ->
// ~2x fewer smem crossbar bytes than the 2-row version.
// V is stored transposed Vt[d][j], stride 260 floats (odd multiple of 16B
// words -> conflict-free per-lane LDS.128 over j).
#define KVS 36
#define VTS 260
#define ATTN_SMEM ((256*KVS + 32*VTS + 16*128 + 16*1024)*4)
__global__ __launch_bounds__(512) void attn_kernel(
    const float* __restrict__ qkv, const float* __restrict__ biasT,
    const unsigned char* __restrict__ mask, float* __restrict__ xa)
{
    extern __shared__ float sm[];
    float* Ks = sm;                        // 256*36   = 9216
    float* Vt = Ks + 256*KVS;              // 32*260   = 8320
    float* Qs = Vt + 32*VTS;               // 16*128   = 2048
    float* Ps = Qs + 16*128;               // 16*1024  = 16384

    int tid  = threadIdx.x;
    int warp = tid >> 5, lane = tid & 31;
    int blk = blockIdx.x;
    int bh = blk >> 1, itile = blk & 1;
    int b = bh >> 3, h = bh & 7;

    const float* base = qkv + (long)b*256*768 + h*32;

    // stage K (row-major, padded) and V transposed
    for (int idx = tid; idx < 2048; idx += 512) {
        int row = idx >> 3, d4 = (idx & 7) << 2;
        *(float4*)&Ks[row*KVS + d4] =
            *(const float4*)(base + (long)row*768 + 256 + d4);
    }
    for (int idx = tid; idx < 8192; idx += 512) {
        int row = idx >> 5, d = idx & 31;
        Vt[d*VTS + row] = base[(long)row*768 + 512 + d];
    }
    __syncthreads();

    unsigned mk = 0;
#pragma unroll
    for (int c = 0; c < 8; c++)
        if (mask[b*256 + c*32 + lane]) mk |= (1u << c);

    float4* qs4 = (float4*)(Qs + warp*128);
    float*  pr  = Ps + warp*1024;
    const float scale = 0.17677669529663687f;   // 1/sqrt(32)

    for (int it2 = 0; it2 < 2; it2++) {
        int i0 = itile*128 + warp*8 + it2*4;    // 4 rows i0..i0+3

        // stage q: 4 rows x 8 float4 = 32 float4, one per lane
        {
            int qr = lane >> 3, qf = lane & 7;
            qs4[lane] = *((const float4*)(base + (long)(i0 + qr)*768) + qf);
        }
        __syncwarp();

        // scores: lane owns keys {c*32+lane}; K pass serves 4 rows
        float a[4][8];
#pragma unroll
        for (int r = 0; r < 4; r++)
#pragma unroll
            for (int c = 0; c < 8; c++) a[r][c] = 0.f;

#pragma unroll
        for (int d4 = 0; d4 < 8; d4++) {
            float4 q0 = qs4[d4];
            float4 q1 = qs4[8 + d4];
            float4 q2 = qs4[16 + d4];
            float4 q3 = qs4[24 + d4];
#pragma unroll
            for (int c = 0; c < 8; c++) {
                float4 k4 = *(const float4*)&Ks[(c*32 + lane)*KVS + d4*4];
                a[0][c] += q0.x*k4.x + q0.y*k4.y + q0.z*k4.z + q0.w*k4.w;
                a[1][c] += q1.x*k4.x + q1.y*k4.y + q1.z*k4.z + q1.w*k4.w;
                a[2][c] += q2.x*k4.x + q2.y*k4.y + q2.z*k4.z + q2.w*k4.w;
                a[3][c] += q3.x*k4.x + q3.y*k4.y + q3.z*k4.z + q3.w*k4.w;
            }
        }

        // bias + mask + softmax per row
        float rz[4];
#pragma unroll
        for (int r = 0; r < 4; r++) {
            const float* brr = biasT + ((long)(bh*256 + i0 + r) << 8);
#pragma unroll
            for (int c = 0; c < 8; c++) {
                a[r][c] = a[r][c]*scale + brr[c*32 + lane];
                if ((mk >> c) & 1) a[r][c] = -1e30f;
            }
            float m = a[r][0];
#pragma unroll
            for (int c = 1; c < 8; c++) m = fmaxf(m, a[r][c]);
#pragma unroll
            for (int o = 16; o > 0; o >>= 1)
                m = fmaxf(m, __shfl_xor_sync(0xffffffffu, m, o));
            float z = 0.f;
#pragma unroll
            for (int c = 0; c < 8; c++) { a[r][c] = __expf(a[r][c] - m); z += a[r][c]; }
#pragma unroll
            for (int o = 16; o > 0; o >>= 1)
                z += __shfl_xor_sync(0xffffffffu, z, o);
            rz[r] = 1.0f / z;
        }

        // exchange P through per-warp smem (4 rows)
#pragma unroll
        for (int r = 0; r < 4; r++)
#pragma unroll
            for (int c = 0; c < 8; c++)
                pr[r*256 + c*32 + lane] = a[r][c];
        __syncwarp();

        // PV: lane owns output dim d = lane; V pass serves 4 rows
        float acc[4] = {0.f, 0.f, 0.f, 0.f};
#pragma unroll
        for (int c = 0; c < 8; c++) {
#pragma unroll
            for (int g = 0; g < 8; g++) {
                float4 v = *(const float4*)&Vt[lane*VTS + c*32 + g*4];
#pragma unroll
                for (int r = 0; r < 4; r++) {
                    float4 P = *(const float4*)&pr[r*256 + c*32 + g*4];
                    acc[r] += P.x*v.x + P.y*v.y + P.z*v.z + P.w*v.w;
                }
            }
        }
        __syncwarp();

#pragma unroll
        for (int r = 0; r < 4; r++)
            xa[(long)(b*256 + i0 + r)*256 + h*32 + lane] = acc[r] * rz[r];
    }
}

// ---------------- launch ----------------
extern "C" void kernel_launch(void* const* d_in, const int* in_sizes, int n_in,
                              void* d_out, int out_size)
{
    const float* x      = (const float*)d_in[0];
    const float* u      = (const float*)d_in[1];
    const unsigned char* mask = (const unsigned char*)d_in[2];
    const float* n1_g   = (const float*)d_in[3];
    const float* n1_b   = (const float*)d_in[4];
    const float* qkv_w  = (const float*)d_in[5];
    const float* qkv_b  = (const float*)d_in[6];
    const float* proj_w = (const float*)d_in[7];
    const float* proj_b = (const float*)d_in[8];
    const float* n2_g   = (const float*)d_in[9];
    const float* n2_b   = (const float*)d_in[10];
    const float* mlp_w1 = (const float*)d_in[11];
    const float* mlp_b1 = (const float*)d_in[12];
    const float* mlp_w2 = (const float*)d_in[13];
    const float* mlp_b2 = (const float*)d_in[14];
    const float* pw_w1  = (const float*)d_in[15];
    const float* pw_b1  = (const float*)d_in[16];
    const float* pw_w2  = (const float*)d_in[17];
    const float* pw_b2  = (const float*)d_in[18];
    const float* pw_w3  = (const float*)d_in[19];
    const float* pw_b3  = (const float*)d_in[20];
    float* out = (float*)d_out;

    float *xn, *qkvb, *biasT, *xa, *x1, *m1;
    cudaGetSymbolAddress((void**)&xn,    g_xn);
    cudaGetSymbolAddress((void**)&qkvb,  g_qkv);
    cudaGetSymbolAddress((void**)&biasT, g_biasT);
    cudaGetSymbolAddress((void**)&xa,    g_xa);
    cudaGetSymbolAddress((void**)&x1,    g_x1);
    cudaGetSymbolAddress((void**)&m1,    g_m1);

    // 1. pairwise MLP (tf32 mma) -> bias[B,H,N,N]
    int pw_smem = (128*H1S + 4096 + 512 + 64 + 8 + 256 + 64) * 4;
    cudaFuncSetAttribute(pairwise_kernel,
                         cudaFuncAttributeMaxDynamicSharedMemorySize, pw_smem);
    pairwise_kernel<<<PAIR_ROWS/128, 256, pw_smem>>>(u, pw_w1, pw_b1, pw_w2, pw_b2,
                                                     pw_w3, pw_b3, biasT);
    // 2. LN1
    ln_kernel<<<ROWS, 256>>>(x, n1_g, n1_b, xn);

    cudaFuncSetAttribute(tgemm_kernel<0>, cudaFuncAttributeMaxDynamicSharedMemorySize, TG_SMEM);
    cudaFuncSetAttribute(tgemm_kernel<1>, cudaFuncAttributeMaxDynamicSharedMemorySize, TG_SMEM);
    cudaFuncSetAttribute(tgemm_kernel<2>, cudaFuncAttributeMaxDynamicSharedMemorySize, TG_SMEM);
    cudaFuncSetAttribute(tgemm_kernel<3>, cudaFuncAttributeMaxDynamicSharedMemorySize, TG_SMEM);

    // 3. QKV GEMM (tf32)  [4096,256] x [256,768]
    tgemm_kernel<0><<<dim3(768/64, ROWS/128), 256, TG_SMEM>>>(xn, qkv_w, qkv_b, nullptr,
                                                              qkvb, ROWS, 768, 256);
    // 4. attention (4-row iterations, transposed V)
    cudaFuncSetAttribute(attn_kernel, cudaFuncAttributeMaxDynamicSharedMemorySize,
                         ATTN_SMEM);
    attn_kernel<<<BB*HH*2, 512, ATTN_SMEM>>>(qkvb, biasT, mask, xa);
    // 5. proj + residual -> x1  (tf32)
    tgemm_kernel<2><<<dim3(256/64, ROWS/128), 256, TG_SMEM>>>(xa, proj_w, proj_b, x,
                                                              x1, ROWS, 256, 256);
    // 6. LN2
    ln_kernel<<<ROWS, 256>>>(x1, n2_g, n2_b, xn);
    // 7. MLP1 + gelu (tf32)
    tgemm_kernel<1><<<dim3(1024/64, ROWS/128), 256, TG_SMEM>>>(xn, mlp_w1, mlp_b1, nullptr,
                                                               m1, ROWS, 1024, 256);
    // 8. MLP2 + gelu + residual -> out (tf32)
    tgemm_kernel<3><<<dim3(256/64, ROWS/128), 256, TG_SMEM>>>(m1, mlp_w2, mlp_b2, x1,
                                                              out, ROWS, 256, 1024);
}